// round 1
// baseline (speedup 1.0000x reference)
#include <cuda_runtime.h>
#include <cuda_bf16.h>

// Problem: out = x + total, where total = n*(n-1)/2 if n>1 else 0,
//          n = trunc(sum(x)), x is 8192x8192 fp32.
//
// Three launches (all graph-capturable, no allocations, no atomics ->
// bit-deterministic across graph replays):
//   1) reduce: per-block double partials into __device__ scratch
//   2) finalize: single block sums partials, computes broadcast total
//   3) add: vectorized float4 broadcast-add

#define REDUCE_BLOCKS 1184   // 148 SMs * 8
#define REDUCE_THREADS 256
#define ADD_THREADS 256

__device__ double g_partials[REDUCE_BLOCKS];
__device__ float  g_total;

__global__ __launch_bounds__(REDUCE_THREADS)
void reduce_kernel(const float4* __restrict__ x4, long long n4) {
    double acc = 0.0;
    long long stride = (long long)gridDim.x * blockDim.x;
    for (long long i = (long long)blockIdx.x * blockDim.x + threadIdx.x;
         i < n4; i += stride) {
        float4 v = x4[i];
        // pair in float first (matches fp32-ish pairwise), then widen
        acc += (double)v.x + (double)v.y + (double)v.z + (double)v.w;
    }
    __shared__ double s[REDUCE_THREADS];
    s[threadIdx.x] = acc;
    __syncthreads();
    #pragma unroll
    for (int off = REDUCE_THREADS / 2; off > 0; off >>= 1) {
        if (threadIdx.x < off) s[threadIdx.x] += s[threadIdx.x + off];
        __syncthreads();
    }
    if (threadIdx.x == 0) g_partials[blockIdx.x] = s[0];
}

__global__ __launch_bounds__(1024)
void finalize_kernel() {
    __shared__ double s[1024];
    double acc = 0.0;
    for (int i = threadIdx.x; i < REDUCE_BLOCKS; i += 1024)
        acc += g_partials[i];
    s[threadIdx.x] = acc;
    __syncthreads();
    #pragma unroll
    for (int off = 512; off > 0; off >>= 1) {
        if (threadIdx.x < off) s[threadIdx.x] += s[threadIdx.x + off];
        __syncthreads();
    }
    if (threadIdx.x == 0) {
        double total_sum = s[0];
        double n = trunc(total_sum);      // int() truncates toward zero
        double total = (n > 1.0) ? n * (n - 1.0) * 0.5 : 0.0;
        g_total = (float)total;
    }
}

__global__ __launch_bounds__(ADD_THREADS)
void add_kernel(const float4* __restrict__ x4, float4* __restrict__ o4,
                long long n4) {
    float t = g_total;
    long long i = (long long)blockIdx.x * blockDim.x + threadIdx.x;
    if (i < n4) {
        float4 v = x4[i];
        v.x += t; v.y += t; v.z += t; v.w += t;
        o4[i] = v;
    }
}

extern "C" void kernel_launch(void* const* d_in, const int* in_sizes, int n_in,
                              void* d_out, int out_size) {
    const float* x = (const float*)d_in[0];
    float* out = (float*)d_out;
    long long n = (long long)in_sizes[0];     // 67108864, divisible by 4
    long long n4 = n / 4;

    reduce_kernel<<<REDUCE_BLOCKS, REDUCE_THREADS>>>((const float4*)x, n4);
    finalize_kernel<<<1, 1024>>>();
    long long add_blocks = (n4 + ADD_THREADS - 1) / ADD_THREADS;
    add_kernel<<<(unsigned)add_blocks, ADD_THREADS>>>((const float4*)x,
                                                      (float4*)out, n4);
}

// round 2
// speedup vs baseline: 2.4904x; 2.4904x over previous
#include <cuda_runtime.h>
#include <cuda_bf16.h>

// out = x + total, total = n*(n-1)/2 if n>1 else 0, n = trunc(sum(x)),
// x: 8192x8192 fp32 (64M elements, 256 MB).
//
// R1 lesson: double-per-element accumulation bound the reduce on the FP64
// pipe (261us @ 13% DRAM). Now: fp32 lane-parallel accumulators, widen to
// double once per thread, deterministic tree combine (no atomics).

#define REDUCE_BLOCKS 1184   // 148 SMs * 8
#define REDUCE_THREADS 256
#define ADD_THREADS 256

__device__ double g_partials[REDUCE_BLOCKS];
__device__ float  g_total;

__global__ __launch_bounds__(REDUCE_THREADS)
void reduce_kernel(const float4* __restrict__ x4, long long n4) {
    // 4 independent fp32 accumulators -> no serialized dependence chain,
    // zero FP64-pipe work in the hot loop.
    float a0 = 0.f, a1 = 0.f, a2 = 0.f, a3 = 0.f;
    long long stride = (long long)gridDim.x * blockDim.x;
    long long i = (long long)blockIdx.x * blockDim.x + threadIdx.x;
    // unroll by 2 for more loads in flight
    for (; i + stride < n4; i += 2 * stride) {
        float4 v = __ldcs(&x4[i]);
        float4 w = __ldcs(&x4[i + stride]);
        a0 += v.x; a1 += v.y; a2 += v.z; a3 += v.w;
        a0 += w.x; a1 += w.y; a2 += w.z; a3 += w.w;
    }
    if (i < n4) {
        float4 v = __ldcs(&x4[i]);
        a0 += v.x; a1 += v.y; a2 += v.z; a3 += v.w;
    }
    // widen once per thread
    double acc = ((double)a0 + (double)a1) + ((double)a2 + (double)a3);

    __shared__ double s[REDUCE_THREADS];
    s[threadIdx.x] = acc;
    __syncthreads();
    #pragma unroll
    for (int off = REDUCE_THREADS / 2; off > 0; off >>= 1) {
        if (threadIdx.x < off) s[threadIdx.x] += s[threadIdx.x + off];
        __syncthreads();
    }
    if (threadIdx.x == 0) g_partials[blockIdx.x] = s[0];
}

__global__ __launch_bounds__(1024)
void finalize_kernel() {
    __shared__ double s[1024];
    double acc = 0.0;
    for (int i = threadIdx.x; i < REDUCE_BLOCKS; i += 1024)
        acc += g_partials[i];
    s[threadIdx.x] = acc;
    __syncthreads();
    #pragma unroll
    for (int off = 512; off > 0; off >>= 1) {
        if (threadIdx.x < off) s[threadIdx.x] += s[threadIdx.x + off];
        __syncthreads();
    }
    if (threadIdx.x == 0) {
        double total_sum = s[0];
        double n = trunc(total_sum);      // int() truncates toward zero
        double total = (n > 1.0) ? n * (n - 1.0) * 0.5 : 0.0;
        g_total = (float)total;
    }
}

__global__ __launch_bounds__(ADD_THREADS)
void add_kernel(const float4* __restrict__ x4, float4* __restrict__ o4,
                long long n4) {
    float t = g_total;
    long long i = (long long)blockIdx.x * blockDim.x + threadIdx.x;
    if (i < n4) {
        float4 v = __ldcs(&x4[i]);
        v.x += t; v.y += t; v.z += t; v.w += t;
        __stcs(&o4[i], v);
    }
}

extern "C" void kernel_launch(void* const* d_in, const int* in_sizes, int n_in,
                              void* d_out, int out_size) {
    const float* x = (const float*)d_in[0];
    float* out = (float*)d_out;
    long long n = (long long)in_sizes[0];     // 67108864, divisible by 4
    long long n4 = n / 4;

    reduce_kernel<<<REDUCE_BLOCKS, REDUCE_THREADS>>>((const float4*)x, n4);
    finalize_kernel<<<1, 1024>>>();
    long long add_blocks = (n4 + ADD_THREADS - 1) / ADD_THREADS;
    add_kernel<<<(unsigned)add_blocks, ADD_THREADS>>>((const float4*)x,
                                                      (float4*)out, n4);
}